// round 1
// baseline (speedup 1.0000x reference)
#include <cuda_runtime.h>
#include <cstdint>

// Problem constants
#define NN 100000   // nodes
#define NH 50000    // hyperedges
#define NI 600000   // incidences
#define DIN 256
#define DH 128
#define NC 40
#define NL 2

// ---------------- scratch (device globals; no allocation at runtime) --------
__device__ __align__(128) float g_x0 [NN * DH];
__device__ __align__(128) float g_x1 [NH * DH];
__device__ __align__(128) float g_m0 [NN * DH];
__device__ __align__(128) float g_m0he[NH * DH];
__device__ __align__(128) float g_m1 [NH * DH];
__device__ __align__(128) float g_m1n [NN * DH];

__device__ __forceinline__ float sigm(float x) {
    return 1.0f / (1.0f + __expf(-x));
}

// ---------------- 128-wide SGEMM:  C[M,128] = A[M,KTOT] @ B[KTOT,128] + bias -
// A is given as two pieces: k in [0,128) from A0 (stride lda0),
// k in [128,KTOT) from A1 (stride lda1).  Lets us feed concat([x1, m0_he]).
template<int KTOT, bool SIG>
__global__ __launch_bounds__(256)
void gemm128(const float* __restrict__ A0, int lda0,
             const float* __restrict__ A1, int lda1,
             const float* __restrict__ B,
             const float* __restrict__ bias,
             float* __restrict__ C, int M)
{
    __shared__ float As[8][128];   // transposed A tile
    __shared__ float Bs[8][128];

    const int tid = threadIdx.x;
    const int tx = tid & 15;        // col group  (8 cols each)
    const int ty = tid >> 4;        // row group  (8 rows each)
    const int block_row = blockIdx.x * 128;

    // A loader: 128 rows x 8 k  -> 256 float4 loads, one per thread
    const int arow = tid >> 1;
    const int acol = (tid & 1) * 4;
    // B loader: 8 k x 128 cols
    const int brow = tid >> 5;
    const int bcol = (tid & 31) * 4;

    float acc[8][8];
    #pragma unroll
    for (int i = 0; i < 8; i++)
        #pragma unroll
        for (int j = 0; j < 8; j++) acc[i][j] = 0.0f;

    for (int k0 = 0; k0 < KTOT; k0 += 8) {
        // ---- load A tile (transposed) ----
        int grow = block_row + arow;
        int kk = k0 + acol;
        float4 av = make_float4(0.f, 0.f, 0.f, 0.f);
        if (grow < M) {
            const float* Ap = (kk < 128)
                ? (A0 + (size_t)grow * lda0 + kk)
                : (A1 + (size_t)grow * lda1 + (kk - 128));
            av = *(const float4*)Ap;
        }
        As[acol + 0][arow] = av.x;
        As[acol + 1][arow] = av.y;
        As[acol + 2][arow] = av.z;
        As[acol + 3][arow] = av.w;

        // ---- load B tile ----
        float4 bv = *(const float4*)(B + (size_t)(k0 + brow) * 128 + bcol);
        *(float4*)&Bs[brow][bcol] = bv;

        __syncthreads();

        #pragma unroll
        for (int kk2 = 0; kk2 < 8; kk2++) {
            float ra[8], rb[8];
            #pragma unroll
            for (int i = 0; i < 8; i++) ra[i] = As[kk2][ty * 8 + i];
            #pragma unroll
            for (int j = 0; j < 8; j++) rb[j] = Bs[kk2][tx * 8 + j];
            #pragma unroll
            for (int i = 0; i < 8; i++)
                #pragma unroll
                for (int j = 0; j < 8; j++)
                    acc[i][j] += ra[i] * rb[j];
        }
        __syncthreads();
    }

    // ---- epilogue: bias (+ sigmoid) ----
    float bvals[8];
    #pragma unroll
    for (int j = 0; j < 8; j++) bvals[j] = bias[tx * 8 + j];

    #pragma unroll
    for (int i = 0; i < 8; i++) {
        int grow = block_row + ty * 8 + i;
        if (grow < M) {
            float v[8];
            #pragma unroll
            for (int j = 0; j < 8; j++) {
                float t = acc[i][j] + bvals[j];
                v[j] = SIG ? sigm(t) : t;
            }
            *(float4*)(C + (size_t)grow * 128 + tx * 8)     = make_float4(v[0], v[1], v[2], v[3]);
            *(float4*)(C + (size_t)grow * 128 + tx * 8 + 4) = make_float4(v[4], v[5], v[6], v[7]);
        }
    }
}

// ---------------- output GEMM: C[M,40] = A[M,128] @ W[128,40] + bias ---------
__global__ __launch_bounds__(256)
void gemm_out(const float* __restrict__ A, const float* __restrict__ W,
              const float* __restrict__ bias, float* __restrict__ C, int M)
{
    __shared__ float Ws[128][40];
    __shared__ float Asm[32][132];   // pad to 132 to kill bank conflicts

    const int tid = threadIdx.x;
    const int row0 = blockIdx.x * 32;

    for (int i = tid; i < 128 * 40; i += 256)
        Ws[i / 40][i % 40] = W[i];

    for (int i = tid; i < 32 * 32; i += 256) {
        int r = i >> 5, c = (i & 31) * 4;
        float4 v = make_float4(0.f, 0.f, 0.f, 0.f);
        if (row0 + r < M) v = *(const float4*)(A + (size_t)(row0 + r) * 128 + c);
        Asm[r][c + 0] = v.x; Asm[r][c + 1] = v.y; Asm[r][c + 2] = v.z; Asm[r][c + 3] = v.w;
    }
    __syncthreads();

    const int r  = tid >> 3;          // 0..31
    const int c0 = (tid & 7) * 5;     // 0,5,...,35
    float acc[5];
    #pragma unroll
    for (int j = 0; j < 5; j++) acc[j] = bias[c0 + j];

    for (int k = 0; k < 128; k++) {
        float a = Asm[r][k];
        #pragma unroll
        for (int j = 0; j < 5; j++) acc[j] += a * Ws[k][c0 + j];
    }

    if (row0 + r < M) {
        #pragma unroll
        for (int j = 0; j < 5; j++)
            C[(size_t)(row0 + r) * 40 + c0 + j] = acc[j];
    }
}

// ---------------- edge scatter: dst[sidx[e]] += vals[e] * src[gidx[e]] ------
__global__ void scatter_kernel(const float* __restrict__ src,
                               const int*   __restrict__ gidx,
                               const int*   __restrict__ sidx,
                               const float* __restrict__ vals,
                               float* __restrict__ dst, int n)
{
    int t = blockIdx.x * blockDim.x + threadIdx.x;
    int e = t >> 5;                 // 32 threads per edge (4 dims each)
    if (e >= n) return;
    int g = (t & 31) << 2;

    float w = __ldg(vals + e);
    const float4 s = *(const float4*)(src + (size_t)__ldg(gidx + e) * 128 + g);
    float* d = dst + (size_t)__ldg(sidx + e) * 128 + g;

    asm volatile("red.global.add.v4.f32 [%0], {%1, %2, %3, %4};"
                 :: "l"(d), "f"(w * s.x), "f"(w * s.y), "f"(w * s.z), "f"(w * s.w)
                 : "memory");
}

// ---------------- elementwise helpers ---------------------------------------
__global__ void zero_kernel(float4* __restrict__ p, int n4)
{
    int i = blockIdx.x * blockDim.x + threadIdx.x;
    if (i < n4) p[i] = make_float4(0.f, 0.f, 0.f, 0.f);
}

__global__ void update_kernel(float4* __restrict__ x, const float4* __restrict__ m, int n4)
{
    int i = blockIdx.x * blockDim.x + threadIdx.x;
    if (i >= n4) return;
    float4 a = x[i];
    float4 b = m[i];
    a.x = sigm(a.x + b.x);
    a.y = sigm(a.y + b.y);
    a.z = sigm(a.z + b.z);
    a.w = sigm(a.w + b.w);
    x[i] = a;
}

// ---------------- host driver ------------------------------------------------
extern "C" void kernel_launch(void* const* d_in, const int* in_sizes, int n_in,
                              void* d_out, int out_size)
{
    const float* x_0      = (const float*)d_in[0];
    const float* x_1      = (const float*)d_in[1];
    const int*   node_idx = (const int*)  d_in[2];
    const int*   he_idx   = (const int*)  d_in[3];
    const float* inc_vals = (const float*)d_in[4];
    const float* W_enc    = (const float*)d_in[5];
    const float* b_enc    = (const float*)d_in[6];
    const float* W_msg0   = (const float*)d_in[7];
    const float* b_msg0   = (const float*)d_in[8];
    const float* W_msg1   = (const float*)d_in[9];
    const float* b_msg1   = (const float*)d_in[10];
    const float* W_out    = (const float*)d_in[11];
    const float* b_out    = (const float*)d_in[12];
    float* out = (float*)d_out;

    float *x0, *x1, *m0, *m0he, *m1, *m1n;
    cudaGetSymbolAddress((void**)&x0,   g_x0);
    cudaGetSymbolAddress((void**)&x1,   g_x1);
    cudaGetSymbolAddress((void**)&m0,   g_m0);
    cudaGetSymbolAddress((void**)&m0he, g_m0he);
    cudaGetSymbolAddress((void**)&m1,   g_m1);
    cudaGetSymbolAddress((void**)&m1n,  g_m1n);

    const int gNN = (NN + 127) / 128;
    const int gNH = (NH + 127) / 128;

    // encode: x0 = x_0 @ W_enc + b ; x1 = x_1 @ W_enc + b
    gemm128<256, false><<<gNN, 256>>>(x_0, 256, x_0 + 128, 256, W_enc, b_enc, x0, NN);
    gemm128<256, false><<<gNH, 256>>>(x_1, 256, x_1 + 128, 256, W_enc, b_enc, x1, NH);

    const int scatter_blocks = ((size_t)NI * 32 + 255) / 256;
    const int z_he  = (NH * DH / 4 + 255) / 256;
    const int z_nn  = (NN * DH / 4 + 255) / 256;

    for (int l = 0; l < NL; l++) {
        // m0 = sigmoid(x0 @ W_msg0[l] + b_msg0[l])
        gemm128<128, true><<<gNN, 256>>>(x0, 128, x0, 128,
                                         W_msg0 + (size_t)l * 128 * 128,
                                         b_msg0 + (size_t)l * 128, m0, NN);
        // m0_he = segment_sum over edges
        zero_kernel<<<z_he, 256>>>((float4*)m0he, NH * DH / 4);
        scatter_kernel<<<scatter_blocks, 256>>>(m0, node_idx, he_idx, inc_vals, m0he, NI);

        // m1 = sigmoid([x1 | m0_he] @ W_msg1[l] + b_msg1[l])
        gemm128<256, true><<<gNH, 256>>>(x1, 128, m0he, 128,
                                         W_msg1 + (size_t)l * 256 * 128,
                                         b_msg1 + (size_t)l * 128, m1, NH);
        // m1_node = segment_sum over edges
        zero_kernel<<<z_nn, 256>>>((float4*)m1n, NN * DH / 4);
        scatter_kernel<<<scatter_blocks, 256>>>(m1, he_idx, node_idx, inc_vals, m1n, NI);

        // x0 = sigmoid(x0 + m1_node); x1 = sigmoid(x1 + m0_he)
        update_kernel<<<z_nn, 256>>>((float4*)x0, (const float4*)m1n, NN * DH / 4);
        update_kernel<<<z_he, 256>>>((float4*)x1, (const float4*)m0he, NH * DH / 4);
    }

    // out = x0 @ W_out + b_out
    gemm_out<<<(NN + 31) / 32, 256>>>(x0, W_out, b_out, out, NN);
}

// round 2
// speedup vs baseline: 1.4657x; 1.4657x over previous
#include <cuda_runtime.h>
#include <cstdint>

// Problem constants
#define NN 100000   // nodes
#define NH 50000    // hyperedges
#define NI 600000   // incidences
#define DIN 256
#define DH 128
#define NC 40
#define NL 2

// ---------------- scratch (device globals; no allocation at runtime) --------
__device__ __align__(128) float g_x0 [NN * DH];
__device__ __align__(128) float g_x1 [NH * DH];
__device__ __align__(128) float g_m0 [NN * DH];
__device__ __align__(128) float g_m0he[NH * DH];
__device__ __align__(128) float g_m1 [NH * DH];
__device__ __align__(128) float g_m1n [NN * DH];

__device__ __forceinline__ float sigm(float x) {
    return 1.0f / (1.0f + __expf(-x));
}

__device__ __forceinline__ uint32_t f2tf32(float v) {
    uint32_t t;
    asm("cvt.rna.tf32.f32 %0, %1;" : "=r"(t) : "f"(v));
    return t;
}

__device__ __forceinline__ void mma_tf32(float (&d)[4], const uint32_t (&a)[4],
                                         const uint32_t (&b)[2]) {
    asm volatile(
        "mma.sync.aligned.m16n8k8.row.col.f32.tf32.tf32.f32 "
        "{%0,%1,%2,%3}, {%4,%5,%6,%7}, {%8,%9}, {%0,%1,%2,%3};"
        : "+f"(d[0]), "+f"(d[1]), "+f"(d[2]), "+f"(d[3])
        : "r"(a[0]), "r"(a[1]), "r"(a[2]), "r"(a[3]), "r"(b[0]), "r"(b[1]));
}

// ---------------- TF32 tensor-core GEMM:  C[M,128] = A[M,KTOT] @ B[KTOT,128] + bias
// A given as two 128-col pieces (k<128 from A0, k>=128 from A1) to support
// concat([x1, m0_he]) without materializing it.
// Block: 128 rows x 128 cols, 256 threads (8 warps in 4x2), warp tile 32x64.
template<int KTOT, bool SIG>
__global__ __launch_bounds__(256, 2)
void gemm128_tc(const float* __restrict__ A0, int lda0,
                const float* __restrict__ A1, int lda1,
                const float* __restrict__ B,
                const float* __restrict__ bias,
                float* __restrict__ C, int M)
{
    // As[row][k] pad to 36 -> frag load banks (lr*4 + lc) all distinct
    // Bs[k][col] pad to 136 -> frag load banks (lc*8 + lr) all distinct
    __shared__ uint32_t As[128][36];
    __shared__ uint32_t Bs[32][136];

    const int tid  = threadIdx.x;
    const int lane = tid & 31;
    const int wid  = tid >> 5;
    const int wm   = wid & 3;        // row group of 32
    const int wn   = wid >> 2;       // col group of 64
    const int lr   = lane >> 2;      // 0..7
    const int lc   = lane & 3;       // 0..3
    const int block_row = blockIdx.x * 128;

    float acc[2][8][4];
    #pragma unroll
    for (int mi = 0; mi < 2; mi++)
        #pragma unroll
        for (int ni = 0; ni < 8; ni++)
            #pragma unroll
            for (int j = 0; j < 4; j++) acc[mi][ni][j] = 0.0f;

    for (int k0 = 0; k0 < KTOT; k0 += 32) {
        // ---- load A tile: 128 rows x 32 k  (1024 float4 / 256 thr = 4 each)
        #pragma unroll
        for (int i = 0; i < 4; i++) {
            int linear = tid + i * 256;
            int r  = linear >> 3;
            int kq = (linear & 7) * 4;
            int grow = block_row + r;
            int gk = k0 + kq;
            float4 v = make_float4(0.f, 0.f, 0.f, 0.f);
            if (grow < M) {
                const float* p = (gk < 128)
                    ? (A0 + (size_t)grow * lda0 + gk)
                    : (A1 + (size_t)grow * lda1 + (gk - 128));
                v = *(const float4*)p;
            }
            uint4 t;
            t.x = f2tf32(v.x); t.y = f2tf32(v.y); t.z = f2tf32(v.z); t.w = f2tf32(v.w);
            *(uint4*)&As[r][kq] = t;
        }
        // ---- load B tile: 32 k x 128 cols
        #pragma unroll
        for (int i = 0; i < 4; i++) {
            int linear = tid + i * 256;
            int kr = linear >> 5;
            int cq = (linear & 31) * 4;
            float4 v = *(const float4*)(B + (size_t)(k0 + kr) * 128 + cq);
            uint4 t;
            t.x = f2tf32(v.x); t.y = f2tf32(v.y); t.z = f2tf32(v.z); t.w = f2tf32(v.w);
            *(uint4*)&Bs[kr][cq] = t;
        }
        __syncthreads();

        #pragma unroll
        for (int ks = 0; ks < 4; ks++) {
            const int kk = ks * 8;
            uint32_t afr[2][4];
            #pragma unroll
            for (int mi = 0; mi < 2; mi++) {
                int r0 = wm * 32 + mi * 16 + lr;
                afr[mi][0] = As[r0    ][kk + lc];
                afr[mi][1] = As[r0 + 8][kk + lc];
                afr[mi][2] = As[r0    ][kk + lc + 4];
                afr[mi][3] = As[r0 + 8][kk + lc + 4];
            }
            uint32_t bfr[8][2];
            #pragma unroll
            for (int ni = 0; ni < 8; ni++) {
                int c0 = wn * 64 + ni * 8 + lr;
                bfr[ni][0] = Bs[kk + lc    ][c0];
                bfr[ni][1] = Bs[kk + lc + 4][c0];
            }
            #pragma unroll
            for (int mi = 0; mi < 2; mi++)
                #pragma unroll
                for (int ni = 0; ni < 8; ni++)
                    mma_tf32(acc[mi][ni], afr[mi], bfr[ni]);
        }
        __syncthreads();
    }

    // ---- epilogue: bias (+ sigmoid), c0/c1 at (row, 2lc/2lc+1), c2/c3 at row+8
    #pragma unroll
    for (int mi = 0; mi < 2; mi++) {
        int r0 = block_row + wm * 32 + mi * 16 + lr;
        #pragma unroll
        for (int ni = 0; ni < 8; ni++) {
            int col = wn * 64 + ni * 8 + 2 * lc;
            float b0 = bias[col], b1 = bias[col + 1];
            float v0 = acc[mi][ni][0] + b0;
            float v1 = acc[mi][ni][1] + b1;
            float v2 = acc[mi][ni][2] + b0;
            float v3 = acc[mi][ni][3] + b1;
            if (SIG) { v0 = sigm(v0); v1 = sigm(v1); v2 = sigm(v2); v3 = sigm(v3); }
            if (r0 < M)
                *(float2*)(C + (size_t)r0 * 128 + col) = make_float2(v0, v1);
            if (r0 + 8 < M)
                *(float2*)(C + (size_t)(r0 + 8) * 128 + col) = make_float2(v2, v3);
        }
    }
}

// ---------------- output GEMM: C[M,40] = A[M,128] @ W[128,40] + bias ---------
__global__ __launch_bounds__(256)
void gemm_out(const float* __restrict__ A, const float* __restrict__ W,
              const float* __restrict__ bias, float* __restrict__ C, int M)
{
    __shared__ float Ws[128][40];
    __shared__ float Asm[32][132];

    const int tid = threadIdx.x;
    const int row0 = blockIdx.x * 32;

    for (int i = tid; i < 128 * 40; i += 256)
        Ws[i / 40][i % 40] = W[i];

    for (int i = tid; i < 32 * 32; i += 256) {
        int r = i >> 5, c = (i & 31) * 4;
        float4 v = make_float4(0.f, 0.f, 0.f, 0.f);
        if (row0 + r < M) v = *(const float4*)(A + (size_t)(row0 + r) * 128 + c);
        Asm[r][c + 0] = v.x; Asm[r][c + 1] = v.y; Asm[r][c + 2] = v.z; Asm[r][c + 3] = v.w;
    }
    __syncthreads();

    const int r  = tid >> 3;
    const int c0 = (tid & 7) * 5;
    float acc[5];
    #pragma unroll
    for (int j = 0; j < 5; j++) acc[j] = bias[c0 + j];

    for (int k = 0; k < 128; k++) {
        float a = Asm[r][k];
        #pragma unroll
        for (int j = 0; j < 5; j++) acc[j] += a * Ws[k][c0 + j];
    }

    if (row0 + r < M) {
        #pragma unroll
        for (int j = 0; j < 5; j++)
            C[(size_t)(row0 + r) * 40 + c0 + j] = acc[j];
    }
}

// ---------------- edge scatter: dst[sidx[e]] += vals[e] * src[gidx[e]] ------
__global__ void scatter_kernel(const float* __restrict__ src,
                               const int*   __restrict__ gidx,
                               const int*   __restrict__ sidx,
                               const float* __restrict__ vals,
                               float* __restrict__ dst, int n)
{
    int t = blockIdx.x * blockDim.x + threadIdx.x;
    int e = t >> 5;                 // 32 threads per edge (4 dims each)
    if (e >= n) return;
    int g = (t & 31) << 2;

    float w = __ldg(vals + e);
    const float4 s = *(const float4*)(src + (size_t)__ldg(gidx + e) * 128 + g);
    float* d = dst + (size_t)__ldg(sidx + e) * 128 + g;

    asm volatile("red.global.add.v4.f32 [%0], {%1, %2, %3, %4};"
                 :: "l"(d), "f"(w * s.x), "f"(w * s.y), "f"(w * s.z), "f"(w * s.w)
                 : "memory");
}

// ---------------- elementwise helpers ---------------------------------------
__global__ void zero_kernel(float4* __restrict__ p, int n4)
{
    int i = blockIdx.x * blockDim.x + threadIdx.x;
    if (i < n4) p[i] = make_float4(0.f, 0.f, 0.f, 0.f);
}

__global__ void update_kernel(float4* __restrict__ x, const float4* __restrict__ m, int n4)
{
    int i = blockIdx.x * blockDim.x + threadIdx.x;
    if (i >= n4) return;
    float4 a = x[i];
    float4 b = m[i];
    a.x = sigm(a.x + b.x);
    a.y = sigm(a.y + b.y);
    a.z = sigm(a.z + b.z);
    a.w = sigm(a.w + b.w);
    x[i] = a;
}

// ---------------- host driver ------------------------------------------------
extern "C" void kernel_launch(void* const* d_in, const int* in_sizes, int n_in,
                              void* d_out, int out_size)
{
    const float* x_0      = (const float*)d_in[0];
    const float* x_1      = (const float*)d_in[1];
    const int*   node_idx = (const int*)  d_in[2];
    const int*   he_idx   = (const int*)  d_in[3];
    const float* inc_vals = (const float*)d_in[4];
    const float* W_enc    = (const float*)d_in[5];
    const float* b_enc    = (const float*)d_in[6];
    const float* W_msg0   = (const float*)d_in[7];
    const float* b_msg0   = (const float*)d_in[8];
    const float* W_msg1   = (const float*)d_in[9];
    const float* b_msg1   = (const float*)d_in[10];
    const float* W_out    = (const float*)d_in[11];
    const float* b_out    = (const float*)d_in[12];
    float* out = (float*)d_out;

    float *x0, *x1, *m0, *m0he, *m1, *m1n;
    cudaGetSymbolAddress((void**)&x0,   g_x0);
    cudaGetSymbolAddress((void**)&x1,   g_x1);
    cudaGetSymbolAddress((void**)&m0,   g_m0);
    cudaGetSymbolAddress((void**)&m0he, g_m0he);
    cudaGetSymbolAddress((void**)&m1,   g_m1);
    cudaGetSymbolAddress((void**)&m1n,  g_m1n);

    const int gNN = (NN + 127) / 128;
    const int gNH = (NH + 127) / 128;

    // encode: x0 = x_0 @ W_enc + b ; x1 = x_1 @ W_enc + b
    gemm128_tc<256, false><<<gNN, 256>>>(x_0, 256, x_0 + 128, 256, W_enc, b_enc, x0, NN);
    gemm128_tc<256, false><<<gNH, 256>>>(x_1, 256, x_1 + 128, 256, W_enc, b_enc, x1, NH);

    const int scatter_blocks = ((size_t)NI * 32 + 255) / 256;
    const int z_he  = (NH * DH / 4 + 255) / 256;
    const int z_nn  = (NN * DH / 4 + 255) / 256;

    for (int l = 0; l < NL; l++) {
        // m0 = sigmoid(x0 @ W_msg0[l] + b_msg0[l])
        gemm128_tc<128, true><<<gNN, 256>>>(x0, 128, x0, 128,
                                            W_msg0 + (size_t)l * 128 * 128,
                                            b_msg0 + (size_t)l * 128, m0, NN);
        // m0_he = segment_sum over edges
        zero_kernel<<<z_he, 256>>>((float4*)m0he, NH * DH / 4);
        scatter_kernel<<<scatter_blocks, 256>>>(m0, node_idx, he_idx, inc_vals, m0he, NI);

        // m1 = sigmoid([x1 | m0_he] @ W_msg1[l] + b_msg1[l])
        gemm128_tc<256, true><<<gNH, 256>>>(x1, 128, m0he, 128,
                                            W_msg1 + (size_t)l * 256 * 128,
                                            b_msg1 + (size_t)l * 128, m1, NH);
        // m1_node = segment_sum over edges
        zero_kernel<<<z_nn, 256>>>((float4*)m1n, NN * DH / 4);
        scatter_kernel<<<scatter_blocks, 256>>>(m1, he_idx, node_idx, inc_vals, m1n, NI);

        // x0 = sigmoid(x0 + m1_node); x1 = sigmoid(x1 + m0_he)
        update_kernel<<<z_nn, 256>>>((float4*)x0, (const float4*)m1n, NN * DH / 4);
        update_kernel<<<z_he, 256>>>((float4*)x1, (const float4*)m0he, NH * DH / 4);
    }

    // out = x0 @ W_out + b_out
    gemm_out<<<(NN + 31) / 32, 256>>>(x0, W_out, b_out, out, NN);
}

// round 3
// speedup vs baseline: 1.7756x; 1.2115x over previous
#include <cuda_runtime.h>
#include <cstdint>

// Problem constants
#define NN 100000   // nodes
#define NH 50000    // hyperedges
#define NI 600000   // incidences
#define DIN 256
#define DH 128
#define NC 40
#define NL 2

// ---------------- scratch (device globals; no allocation at runtime) --------
__device__ __align__(128) float g_x0 [NN * DH];
__device__ __align__(128) float g_x1 [NH * DH];
__device__ __align__(128) float g_m0 [NN * DH];
__device__ __align__(128) float g_m0he[NH * DH];
__device__ __align__(128) float g_m1 [NH * DH];
__device__ __align__(128) float g_m1n [NN * DH];

__device__ __forceinline__ float sigm(float x) {
    return 1.0f / (1.0f + __expf(-x));
}

__device__ __forceinline__ void mma_tf32(float (&d)[4], const uint32_t (&a)[4],
                                         const uint32_t (&b)[2]) {
    asm volatile(
        "mma.sync.aligned.m16n8k8.row.col.f32.tf32.tf32.f32 "
        "{%0,%1,%2,%3}, {%4,%5,%6,%7}, {%8,%9}, {%0,%1,%2,%3};"
        : "+f"(d[0]), "+f"(d[1]), "+f"(d[2]), "+f"(d[3])
        : "r"(a[0]), "r"(a[1]), "r"(a[2]), "r"(a[3]), "r"(b[0]), "r"(b[1]));
}

__device__ __forceinline__ void cp16(uint32_t dst, const void* src, int szbytes) {
    asm volatile("cp.async.cg.shared.global [%0], [%1], 16, %2;"
                 :: "r"(dst), "l"(src), "r"(szbytes));
}

// SMEM geometry (uint32 words)
#define AS_ROWP 36          // 128 rows x 36 (pad) per stage
#define BS_ROWP 136         // 32 k x 136 (pad) per stage
#define AS_STAGE (128 * AS_ROWP)
#define BS_STAGE (32 * BS_ROWP)
#define SMEM_WORDS (2 * AS_STAGE + 2 * BS_STAGE)
#define SMEM_BYTES (SMEM_WORDS * 4)

// ---------------- TF32 tensor-core GEMM:  C[M,128] = A[M,KTOT] @ B[KTOT,128] + bias
// Non-FUSE: A given as two 128-col pieces (k<128 from A0, k>=128 from A1).
// FUSE: KTOT=128, A = sigmoid(A0 + A1) computed on load; result written back to A0
//       (each row is touched by exactly one block -> race-free, deterministic).
// Block: 128 rows x 128 cols, 256 threads (8 warps 4x2), warp tile 32x64,
// 2-stage cp.async pipeline, raw fp32 bits as tf32 (HW truncation).
template<int KTOT, bool SIG, bool FUSE>
__global__ __launch_bounds__(256, 2)
void gemm128_tc(const float* __restrict__ A0, int lda0,
                const float* __restrict__ A1, int lda1,
                float* __restrict__ Awb,
                const float* __restrict__ B,
                const float* __restrict__ bias,
                float* __restrict__ C, int M)
{
    extern __shared__ uint32_t smem[];
    uint32_t* AsBase = smem;                    // [2][128][36]
    uint32_t* BsBase = smem + 2 * AS_STAGE;     // [2][32][136]

    uint32_t smem_u32;
    {
        asm("{ .reg .u64 t; cvta.to.shared.u64 t, %1; cvt.u32.u64 %0, t; }"
            : "=r"(smem_u32) : "l"(smem));
    }
    const uint32_t as_addr = smem_u32;
    const uint32_t bs_addr = smem_u32 + 2 * AS_STAGE * 4;

    const int tid  = threadIdx.x;
    const int lane = tid & 31;
    const int wid  = tid >> 5;
    const int wm   = wid & 3;        // row group of 32
    const int wn   = wid >> 2;       // col group of 64
    const int lr   = lane >> 2;      // 0..7
    const int lc   = lane & 3;       // 0..3
    const int block_row = blockIdx.x * 128;

    constexpr int NCHUNK = KTOT / 32;

    float acc[2][8][4];
    #pragma unroll
    for (int mi = 0; mi < 2; mi++)
        #pragma unroll
        for (int ni = 0; ni < 8; ni++)
            #pragma unroll
            for (int j = 0; j < 4; j++) acc[mi][ni][j] = 0.0f;

    // loader index precompute
    const int arow = tid >> 3;           // base row for i=0 (0..31), +32 per i
    const int akq  = (tid & 7) * 4;
    const int bkr  = tid >> 5;           // base k for i=0 (0..7), +8 per i
    const int bcq  = (tid & 31) * 4;

    auto prefetch = [&](int c, int s) {
        const int k0 = c * 32;
        // ---- A tile: 128 rows x 32 k ----
        #pragma unroll
        for (int i = 0; i < 4; i++) {
            const int r    = arow + i * 32;
            const int grow = block_row + r;
            const int gk   = k0 + akq;
            const uint32_t dst = as_addr + (((s * 128 + r) * AS_ROWP) + akq) * 4;
            if (!FUSE) {
                const float* p = (gk < 128)
                    ? (A0 + (size_t)grow * lda0 + gk)
                    : (A1 + (size_t)grow * lda1 + (gk - 128));
                if (grow >= M) p = A0;           // keep address valid
                cp16(dst, p, grow < M ? 16 : 0); // zero-fill OOB rows
            } else {
                float4 v = make_float4(0.f, 0.f, 0.f, 0.f);
                if (grow < M) {
                    const float4 a = *(const float4*)(A0 + (size_t)grow * 128 + gk);
                    const float4 b = *(const float4*)(A1 + (size_t)grow * 128 + gk);
                    v.x = sigm(a.x + b.x); v.y = sigm(a.y + b.y);
                    v.z = sigm(a.z + b.z); v.w = sigm(a.w + b.w);
                    *(float4*)(Awb + (size_t)grow * 128 + gk) = v;
                }
                asm volatile("st.shared.v4.b32 [%0], {%1,%2,%3,%4};"
                             :: "r"(dst), "r"(__float_as_uint(v.x)), "r"(__float_as_uint(v.y)),
                                "r"(__float_as_uint(v.z)), "r"(__float_as_uint(v.w)));
            }
        }
        // ---- B tile: 32 k x 128 cols ----
        #pragma unroll
        for (int i = 0; i < 4; i++) {
            const int kr = bkr + i * 8;
            const uint32_t dst = bs_addr + (((s * 32 + kr) * BS_ROWP) + bcq) * 4;
            cp16(dst, B + (size_t)(k0 + kr) * 128 + bcq, 16);
        }
    };

    prefetch(0, 0);
    asm volatile("cp.async.commit_group;");

    for (int c = 0; c < NCHUNK; c++) {
        const int s = c & 1;
        if (c + 1 < NCHUNK) {
            prefetch(c + 1, s ^ 1);
            asm volatile("cp.async.commit_group;");
            asm volatile("cp.async.wait_group 1;");
        } else {
            asm volatile("cp.async.wait_group 0;");
        }
        __syncthreads();

        const uint32_t (*As)[AS_ROWP] =
            reinterpret_cast<const uint32_t(*)[AS_ROWP]>(AsBase + s * AS_STAGE);
        const uint32_t (*Bs)[BS_ROWP] =
            reinterpret_cast<const uint32_t(*)[BS_ROWP]>(BsBase + s * BS_STAGE);

        #pragma unroll
        for (int ks = 0; ks < 4; ks++) {
            const int kk = ks * 8;
            uint32_t afr[2][4];
            #pragma unroll
            for (int mi = 0; mi < 2; mi++) {
                const int r0 = wm * 32 + mi * 16 + lr;
                afr[mi][0] = As[r0    ][kk + lc];
                afr[mi][1] = As[r0 + 8][kk + lc];
                afr[mi][2] = As[r0    ][kk + lc + 4];
                afr[mi][3] = As[r0 + 8][kk + lc + 4];
            }
            uint32_t bfr[8][2];
            #pragma unroll
            for (int ni = 0; ni < 8; ni++) {
                const int c0 = wn * 64 + ni * 8 + lr;
                bfr[ni][0] = Bs[kk + lc    ][c0];
                bfr[ni][1] = Bs[kk + lc + 4][c0];
            }
            #pragma unroll
            for (int mi = 0; mi < 2; mi++)
                #pragma unroll
                for (int ni = 0; ni < 8; ni++)
                    mma_tf32(acc[mi][ni], afr[mi], bfr[ni]);
        }
        __syncthreads();
    }

    // ---- epilogue: bias (+ sigmoid) ----
    #pragma unroll
    for (int mi = 0; mi < 2; mi++) {
        const int r0 = block_row + wm * 32 + mi * 16 + lr;
        #pragma unroll
        for (int ni = 0; ni < 8; ni++) {
            const int col = wn * 64 + ni * 8 + 2 * lc;
            const float b0 = bias[col], b1 = bias[col + 1];
            float v0 = acc[mi][ni][0] + b0;
            float v1 = acc[mi][ni][1] + b1;
            float v2 = acc[mi][ni][2] + b0;
            float v3 = acc[mi][ni][3] + b1;
            if (SIG) { v0 = sigm(v0); v1 = sigm(v1); v2 = sigm(v2); v3 = sigm(v3); }
            if (r0 < M)
                *(float2*)(C + (size_t)r0 * 128 + col) = make_float2(v0, v1);
            if (r0 + 8 < M)
                *(float2*)(C + (size_t)(r0 + 8) * 128 + col) = make_float2(v2, v3);
        }
    }
}

// ---------------- output GEMM: C[M,40] = sigm(A+Mx) @ W[128,40] + bias -------
template<bool FUSE>
__global__ __launch_bounds__(256)
void gemm_out(const float* __restrict__ A, const float* __restrict__ Mx,
              const float* __restrict__ W,
              const float* __restrict__ bias, float* __restrict__ C, int M)
{
    __shared__ float Ws[128][40];
    __shared__ float Asm[32][132];

    const int tid = threadIdx.x;
    const int row0 = blockIdx.x * 32;

    for (int i = tid; i < 128 * 40; i += 256)
        Ws[i / 40][i % 40] = W[i];

    for (int i = tid; i < 32 * 32; i += 256) {
        int r = i >> 5, c = (i & 31) * 4;
        float4 v = make_float4(0.f, 0.f, 0.f, 0.f);
        if (row0 + r < M) {
            v = *(const float4*)(A + (size_t)(row0 + r) * 128 + c);
            if (FUSE) {
                const float4 m = *(const float4*)(Mx + (size_t)(row0 + r) * 128 + c);
                v.x = sigm(v.x + m.x); v.y = sigm(v.y + m.y);
                v.z = sigm(v.z + m.z); v.w = sigm(v.w + m.w);
            }
        }
        Asm[r][c + 0] = v.x; Asm[r][c + 1] = v.y; Asm[r][c + 2] = v.z; Asm[r][c + 3] = v.w;
    }
    __syncthreads();

    const int r  = tid >> 3;
    const int c0 = (tid & 7) * 5;
    float acc[5];
    #pragma unroll
    for (int j = 0; j < 5; j++) acc[j] = bias[c0 + j];

    for (int k = 0; k < 128; k++) {
        float a = Asm[r][k];
        #pragma unroll
        for (int j = 0; j < 5; j++) acc[j] += a * Ws[k][c0 + j];
    }

    if (row0 + r < M) {
        #pragma unroll
        for (int j = 0; j < 5; j++)
            C[(size_t)(row0 + r) * 40 + c0 + j] = acc[j];
    }
}

// ---------------- edge scatter: dst[sidx[e]] += vals[e] * src[gidx[e]] ------
__global__ void scatter_kernel(const float* __restrict__ src,
                               const int*   __restrict__ gidx,
                               const int*   __restrict__ sidx,
                               const float* __restrict__ vals,
                               float* __restrict__ dst, int n)
{
    int t = blockIdx.x * blockDim.x + threadIdx.x;
    int e = t >> 5;                 // 32 threads per edge (4 dims each)
    if (e >= n) return;
    int g = (t & 31) << 2;

    float w = __ldg(vals + e);
    const float4 s = *(const float4*)(src + (size_t)__ldg(gidx + e) * 128 + g);
    float* d = dst + (size_t)__ldg(sidx + e) * 128 + g;

    asm volatile("red.global.add.v4.f32 [%0], {%1, %2, %3, %4};"
                 :: "l"(d), "f"(w * s.x), "f"(w * s.y), "f"(w * s.z), "f"(w * s.w)
                 : "memory");
}

// ---------------- elementwise update (x = sigm(x + m)) ----------------------
__global__ void update_kernel(float4* __restrict__ x, const float4* __restrict__ m, int n4)
{
    int i = blockIdx.x * blockDim.x + threadIdx.x;
    if (i >= n4) return;
    float4 a = x[i];
    float4 b = m[i];
    a.x = sigm(a.x + b.x);
    a.y = sigm(a.y + b.y);
    a.z = sigm(a.z + b.z);
    a.w = sigm(a.w + b.w);
    x[i] = a;
}

// ---------------- host driver ------------------------------------------------
extern "C" void kernel_launch(void* const* d_in, const int* in_sizes, int n_in,
                              void* d_out, int out_size)
{
    const float* x_0      = (const float*)d_in[0];
    const float* x_1      = (const float*)d_in[1];
    const int*   node_idx = (const int*)  d_in[2];
    const int*   he_idx   = (const int*)  d_in[3];
    const float* inc_vals = (const float*)d_in[4];
    const float* W_enc    = (const float*)d_in[5];
    const float* b_enc    = (const float*)d_in[6];
    const float* W_msg0   = (const float*)d_in[7];
    const float* b_msg0   = (const float*)d_in[8];
    const float* W_msg1   = (const float*)d_in[9];
    const float* b_msg1   = (const float*)d_in[10];
    const float* W_out    = (const float*)d_in[11];
    const float* b_out    = (const float*)d_in[12];
    float* out = (float*)d_out;

    float *x0, *x1, *m0, *m0he, *m1, *m1n;
    cudaGetSymbolAddress((void**)&x0,   g_x0);
    cudaGetSymbolAddress((void**)&x1,   g_x1);
    cudaGetSymbolAddress((void**)&m0,   g_m0);
    cudaGetSymbolAddress((void**)&m0he, g_m0he);
    cudaGetSymbolAddress((void**)&m1,   g_m1);
    cudaGetSymbolAddress((void**)&m1n,  g_m1n);

    static int smem_set = 0;
    if (!smem_set) {
        cudaFuncSetAttribute(gemm128_tc<256, false, false>,
                             cudaFuncAttributeMaxDynamicSharedMemorySize, SMEM_BYTES);
        cudaFuncSetAttribute(gemm128_tc<128, true, false>,
                             cudaFuncAttributeMaxDynamicSharedMemorySize, SMEM_BYTES);
        cudaFuncSetAttribute(gemm128_tc<256, true, false>,
                             cudaFuncAttributeMaxDynamicSharedMemorySize, SMEM_BYTES);
        cudaFuncSetAttribute(gemm128_tc<128, true, true>,
                             cudaFuncAttributeMaxDynamicSharedMemorySize, SMEM_BYTES);
        smem_set = 1;
    }

    const int gNN = (NN + 127) / 128;
    const int gNH = (NH + 127) / 128;
    const int scatter_blocks = (int)(((size_t)NI * 32 + 255) / 256);

    // encode: x0 = x_0 @ W_enc + b ; x1 = x_1 @ W_enc + b
    gemm128_tc<256, false, false><<<gNN, 256, SMEM_BYTES>>>(
        x_0, 256, x_0 + 128, 256, nullptr, W_enc, b_enc, x0, NN);
    gemm128_tc<256, false, false><<<gNH, 256, SMEM_BYTES>>>(
        x_1, 256, x_1 + 128, 256, nullptr, W_enc, b_enc, x1, NH);

    // ---------------- layer 0 ----------------
    gemm128_tc<128, true, false><<<gNN, 256, SMEM_BYTES>>>(
        x0, 128, x0, 128, nullptr, W_msg0, b_msg0, m0, NN);
    cudaMemsetAsync(m0he, 0, (size_t)NH * DH * sizeof(float));
    scatter_kernel<<<scatter_blocks, 256>>>(m0, node_idx, he_idx, inc_vals, m0he, NI);

    gemm128_tc<256, true, false><<<gNH, 256, SMEM_BYTES>>>(
        x1, 128, m0he, 128, nullptr, W_msg1, b_msg1, m1, NH);
    cudaMemsetAsync(m1n, 0, (size_t)NN * DH * sizeof(float));
    scatter_kernel<<<scatter_blocks, 256>>>(m1, he_idx, node_idx, inc_vals, m1n, NI);

    // x1 = sigm(x1 + m0he)   (needed by layer-1 m1 GEMM before m0he is overwritten)
    update_kernel<<<(NH * DH / 4 + 255) / 256, 256>>>(
        (float4*)x1, (const float4*)m0he, NH * DH / 4);
    // x0 update deferred: fused into layer-1 m0 GEMM.

    // ---------------- layer 1 ----------------
    // m0 = sigm( sigm(x0+m1n) @ W ); also writes x0 <- sigm(x0+m1n)
    gemm128_tc<128, true, true><<<gNN, 256, SMEM_BYTES>>>(
        x0, 128, m1n, 128, x0, W_msg0 + 128 * 128, b_msg0 + 128, m0, NN);
    cudaMemsetAsync(m0he, 0, (size_t)NH * DH * sizeof(float));
    scatter_kernel<<<scatter_blocks, 256>>>(m0, node_idx, he_idx, inc_vals, m0he, NI);

    gemm128_tc<256, true, false><<<gNH, 256, SMEM_BYTES>>>(
        x1, 128, m0he, 128, nullptr, W_msg1 + 256 * 128, b_msg1 + 128, m1, NH);
    cudaMemsetAsync(m1n, 0, (size_t)NN * DH * sizeof(float));
    scatter_kernel<<<scatter_blocks, 256>>>(m1, he_idx, node_idx, inc_vals, m1n, NI);

    // x1 layer-1 update is dead (x1 unused afterwards) -> skipped.
    // x0 layer-1 update fused into the output GEMM below.

    // out = sigm(x0 + m1n) @ W_out + b_out
    gemm_out<true><<<(NN + 31) / 32, 256>>>(x0, m1n, W_out, b_out, out, NN);
}